// round 12
// baseline (speedup 1.0000x reference)
#include <cuda_runtime.h>

// PMLoss, 2-D tiled, single fused kernel, scalar inner loop.
// B=128 ROIs, C=22 classes, P=1024 points.
// grid 4096 = 128b x 4 p-chunks x 8 q-chunks, TPB=128, 2 p/thread,
// 128-q tiles. ~2 waves -> hardware work-stealing balances the heavy tail.
// Heavy block: partial min over its 128-q float4 smem tile -> g_dmin[b][qc][p].
// Light block (qc==0 only): pointwise d -> g_dmin[b][0][p].
// 32nd block of each b: min-over-qc + sum -> g_partials[b].
// Last combine block overall: final 128-way sum -> out; resets tickets.

#define NB 128
#define NC 22
#define NP 1024
#define PC 4
#define QC 8
#define PPB (NP / PC)     // 256 p per block
#define QPB (NP / QC)     // 128 q per block
#define TPB 128
#define GRID1 (NB * PC * QC)   // 4096

__device__ float g_dmin[NB][QC][NP];   // 4 MB scratch
__device__ float g_partials[NB];
__device__ int   g_ticket_b[NB];
__device__ unsigned int g_ticket = 0;

__device__ __forceinline__ void quat2mat(float w, float x, float y, float z,
                                         float* R) {
    R[0] = 1.f - 2.f * (y * y + z * z);
    R[1] = 2.f * (x * y - w * z);
    R[2] = 2.f * (x * z + w * y);
    R[3] = 2.f * (x * y + w * z);
    R[4] = 1.f - 2.f * (x * x + z * z);
    R[5] = 2.f * (y * z - w * x);
    R[6] = 2.f * (x * z - w * y);
    R[7] = 2.f * (y * z + w * x);
    R[8] = 1.f - 2.f * (x * x + y * y);
}

__device__ __forceinline__ float block_reduce_128(float d, float* s_red,
                                                  int tid) {
#pragma unroll
    for (int o = 16; o > 0; o >>= 1) d += __shfl_down_sync(0xffffffffu, d, o);
    if ((tid & 31) == 0) s_red[tid >> 5] = d;
    __syncthreads();
    if (tid < 4) {
        d = s_red[tid];
        d += __shfl_down_sync(0xfu, d, 2);
        d += __shfl_down_sync(0xfu, d, 1);
    }
    return d;
}

__global__ __launch_bounds__(TPB) void pm_fused_kernel(
    const float* __restrict__ pred, const float* __restrict__ tgt,
    const float* __restrict__ wt, const float* __restrict__ pts,
    const float* __restrict__ sym, float* __restrict__ out) {
    __shared__ float4 s_pt[QPB];      // target-rotated q tile: (x,y,z,|t|^2)
    __shared__ float sR[18];          // Rp 0..8, Rt 9..17
    __shared__ int s_cls, s_issym;
    __shared__ float s_red[4];
    __shared__ int s_lastb, s_lastg;

    const int bid = blockIdx.x;
    const int b = bid >> 5;
    const int pc = (bid >> 3) & 3;
    const int qc = bid & 7;
    const int tid = threadIdx.x;

    // ---- setup: parallel class find (warp 0), quat->mat (lane 0) ----
    if (tid < 32) {
        bool hit = (tid >= 1) && (tid < NC) &&
                   (wt[b * 4 * NC + 4 * tid] > 0.5f);
        unsigned m = __ballot_sync(0xffffffffu, hit);
        if (tid == 0) {
            int cls = m ? (__ffs(m) - 1) : 0;
            s_cls = cls;
            s_issym = (sym[cls] > 0.0f) ? 1 : 0;
            const float* qp = pred + b * 4 * NC + cls * 4;
            float qw = qp[0], qx = qp[1], qy = qp[2], qz = qp[3];
            float inv = rsqrtf(qw * qw + qx * qx + qy * qy + qz * qz);
            quat2mat(qw * inv, qx * inv, qy * inv, qz * inv, sR);
            const float* qt = tgt + b * 4 * NC + cls * 4;  // unit-norm
            quat2mat(qt[0], qt[1], qt[2], qt[3], sR + 9);
        }
    }
    __syncthreads();

    const int issym = s_issym;
    const int cls = s_cls;
    const float* __restrict__ mp = pts + (size_t)cls * NP * 3;
    const int p0 = pc * PPB + tid;    // this thread's two p's
    const int p1 = p0 + TPB;

    if (!issym) {
        if (qc == 0) {
            // Pointwise |(Rp-Rt) x|^2 for p0, p1.
            float D0 = sR[0] - sR[9],  D1 = sR[1] - sR[10],
                  D2 = sR[2] - sR[11];
            float D3 = sR[3] - sR[12], D4 = sR[4] - sR[13],
                  D5 = sR[5] - sR[14];
            float D6 = sR[6] - sR[15], D7 = sR[7] - sR[16],
                  D8 = sR[8] - sR[17];
#pragma unroll
            for (int pi = 0; pi < 2; pi++) {
                int p = pi ? p1 : p0;
                float x = mp[3 * p + 0], y = mp[3 * p + 1], z = mp[3 * p + 2];
                float dx = D0 * x + D1 * y + D2 * z;
                float dy = D3 * x + D4 * y + D5 * z;
                float dz = D6 * x + D7 * y + D8 * z;
                g_dmin[b][0][p] = dx * dx + dy * dy + dz * dz;
            }
        }
    } else {
        // ---- heavy: fill this block's 128-q target tile ----
        if (tid < QPB) {
            float T0 = sR[9],  T1 = sR[10], T2 = sR[11];
            float T3 = sR[12], T4 = sR[13], T5 = sR[14];
            float T6 = sR[15], T7 = sR[16], T8 = sR[17];
            int q = qc * QPB + tid;
            float x = mp[3 * q + 0], y = mp[3 * q + 1], z = mp[3 * q + 2];
            float tx = T0 * x + T1 * y + T2 * z;
            float ty = T3 * x + T4 * y + T5 * z;
            float tz = T6 * x + T7 * y + T8 * z;
            s_pt[tid] = make_float4(tx, ty, tz, tx * tx + ty * ty + tz * tz);
        }
        // predicted-rotated p0, p1
        float px0, py0, pz0, px1, py1, pz1;
        {
            float P0 = sR[0], P1 = sR[1], P2 = sR[2];
            float P3 = sR[3], P4 = sR[4], P5 = sR[5];
            float P6 = sR[6], P7 = sR[7], P8 = sR[8];
            float x = mp[3 * p0 + 0], y = mp[3 * p0 + 1], z = mp[3 * p0 + 2];
            px0 = P0 * x + P1 * y + P2 * z;
            py0 = P3 * x + P4 * y + P5 * z;
            pz0 = P6 * x + P7 * y + P8 * z;
            x = mp[3 * p1 + 0]; y = mp[3 * p1 + 1]; z = mp[3 * p1 + 2];
            px1 = P0 * x + P1 * y + P2 * z;
            py1 = P3 * x + P4 * y + P5 * z;
            pz1 = P6 * x + P7 * y + P8 * z;
        }
        __syncthreads();

        const float a0x = -2.f * px0, a0y = -2.f * py0, a0z = -2.f * pz0;
        const float a1x = -2.f * px1, a1y = -2.f * py1, a1z = -2.f * pz1;
        const float INF = 3.402823466e38f;
        float m0a = INF, m0b = INF, m1a = INF, m1b = INF;

#pragma unroll 4
        for (int j = 0; j < QPB / 2; j++) {
            float4 t0 = s_pt[2 * j];
            float4 t1 = s_pt[2 * j + 1];
            float v;
            v = fmaf(a0x, t0.x, t0.w);
            v = fmaf(a0y, t0.y, v);
            v = fmaf(a0z, t0.z, v);
            m0a = fminf(m0a, v);
            v = fmaf(a1x, t0.x, t0.w);
            v = fmaf(a1y, t0.y, v);
            v = fmaf(a1z, t0.z, v);
            m1a = fminf(m1a, v);
            v = fmaf(a0x, t1.x, t1.w);
            v = fmaf(a0y, t1.y, v);
            v = fmaf(a0z, t1.z, v);
            m0b = fminf(m0b, v);
            v = fmaf(a1x, t1.x, t1.w);
            v = fmaf(a1y, t1.y, v);
            v = fmaf(a1z, t1.z, v);
            m1b = fminf(m1b, v);
        }
        g_dmin[b][qc][p0] =
            fminf(m0a, m0b) + (px0 * px0 + py0 * py0 + pz0 * pz0);
        g_dmin[b][qc][p1] =
            fminf(m1a, m1b) + (px1 * px1 + py1 * py1 + pz1 * pz1);
    }

    // ---- release + per-b ticket ----
    __threadfence();           // make this block's g_dmin stores visible
    __syncthreads();
    if (tid == 0) {
        int t = atomicAdd(&g_ticket_b[b], 1);
        s_lastb = (t == PC * QC - 1) ? 1 : 0;
    }
    __syncthreads();
    if (!s_lastb) return;

    // ---- combine for ROI b (last of its 32 blocks; data is L2-hot) ----
    __threadfence();           // acquire
    float acc = 0.f;
#pragma unroll
    for (int i = 0; i < NP / TPB; i++) {
        int p = tid + i * TPB;
        float dv = __ldcg(&g_dmin[b][0][p]);
        if (issym) {
#pragma unroll
            for (int k = 1; k < QC; k++)
                dv = fminf(dv, __ldcg(&g_dmin[b][k][p]));
        }
        acc += dv;
    }
    float tot = block_reduce_128(acc, s_red, tid);
    if (tid == 0) {
        g_partials[b] = tot;
        __threadfence();
        unsigned t = atomicAdd(&g_ticket, 1u);
        s_lastg = (t == NB - 1) ? 1 : 0;
    }
    __syncthreads();
    if (!s_lastg) return;

    // ---- final: fixed-order 128-way sum, write scalar, reset tickets ----
    __threadfence();           // acquire
    float v = __ldcg(&g_partials[tid]);
    float total = block_reduce_128(v, s_red, tid);
    g_ticket_b[tid] = 0;       // reset per-b tickets for next replay
    if (tid == 0) {
        out[0] = total * (1.0f / (2.0f * NB * NP));
        g_ticket = 0;
    }
}

extern "C" void kernel_launch(void* const* d_in, const int* in_sizes, int n_in,
                              void* d_out, int out_size) {
    const float* pred = (const float*)d_in[0];
    const float* tgt  = (const float*)d_in[1];
    const float* wt   = (const float*)d_in[2];
    const float* pts  = (const float*)d_in[3];
    const float* sym  = (const float*)d_in[4];
    float* out = (float*)d_out;

    pm_fused_kernel<<<GRID1, TPB>>>(pred, tgt, wt, pts, sym, out);
}

// round 13
// speedup vs baseline: 1.0384x; 1.0384x over previous
#include <cuda_runtime.h>

// PMLoss, 2-D tiled, single fused kernel, scalar inner loop.
// B=128 ROIs, C=22 classes, P=1024 points.
// grid 2048 = 128b x 4 p-chunks x 4 q-chunks, TPB=128, 2 p/thread.
// Heavy block: partial min over its 256-q float4 smem tile -> g_dmin[b][qc][p].
// Light block (qc==0 only): pointwise d -> g_dmin[b][0][p].
// Ticket protocol uses tid0-ONLY gpu fences (CUB last-block pattern):
// __syncthreads() orders all threads' stores; tid0 fence+atomic releases them.
// 16th block of each b: min-over-qc + sum -> g_partials[b].
// Last combine block overall: final 128-way sum -> out; resets tickets.

#define NB 128
#define NC 22
#define NP 1024
#define PC 4
#define QC 4
#define PPB (NP / PC)     // 256 p per block
#define QPB (NP / QC)     // 256 q per block
#define TPB 128
#define GRID1 (NB * PC * QC)   // 2048

__device__ float g_dmin[NB][QC][NP];   // 2 MB scratch
__device__ float g_partials[NB];
__device__ int   g_ticket_b[NB];
__device__ unsigned int g_ticket = 0;

__device__ __forceinline__ void quat2mat(float w, float x, float y, float z,
                                         float* R) {
    R[0] = 1.f - 2.f * (y * y + z * z);
    R[1] = 2.f * (x * y - w * z);
    R[2] = 2.f * (x * z + w * y);
    R[3] = 2.f * (x * y + w * z);
    R[4] = 1.f - 2.f * (x * x + z * z);
    R[5] = 2.f * (y * z - w * x);
    R[6] = 2.f * (x * z - w * y);
    R[7] = 2.f * (y * z + w * x);
    R[8] = 1.f - 2.f * (x * x + y * y);
}

__device__ __forceinline__ float block_reduce_128(float d, float* s_red,
                                                  int tid) {
#pragma unroll
    for (int o = 16; o > 0; o >>= 1) d += __shfl_down_sync(0xffffffffu, d, o);
    if ((tid & 31) == 0) s_red[tid >> 5] = d;
    __syncthreads();
    if (tid < 4) {
        d = s_red[tid];
        d += __shfl_down_sync(0xfu, d, 2);
        d += __shfl_down_sync(0xfu, d, 1);
    }
    return d;
}

__global__ __launch_bounds__(TPB) void pm_fused_kernel(
    const float* __restrict__ pred, const float* __restrict__ tgt,
    const float* __restrict__ wt, const float* __restrict__ pts,
    const float* __restrict__ sym, float* __restrict__ out) {
    __shared__ float4 s_pt[QPB];      // target-rotated q tile: (x,y,z,|t|^2)
    __shared__ float sR[18];          // Rp 0..8, Rt 9..17
    __shared__ int s_cls, s_issym;
    __shared__ float s_red[4];
    __shared__ int s_lastb, s_lastg;

    const int bid = blockIdx.x;
    const int b = bid >> 4;
    const int pc = (bid >> 2) & 3;
    const int qc = bid & 3;
    const int tid = threadIdx.x;

    // ---- setup: parallel class find (warp 0), quat->mat (lane 0) ----
    if (tid < 32) {
        bool hit = (tid >= 1) && (tid < NC) &&
                   (wt[b * 4 * NC + 4 * tid] > 0.5f);
        unsigned m = __ballot_sync(0xffffffffu, hit);
        if (tid == 0) {
            int cls = m ? (__ffs(m) - 1) : 0;
            s_cls = cls;
            s_issym = (sym[cls] > 0.0f) ? 1 : 0;
            const float* qp = pred + b * 4 * NC + cls * 4;
            float qw = qp[0], qx = qp[1], qy = qp[2], qz = qp[3];
            float inv = rsqrtf(qw * qw + qx * qx + qy * qy + qz * qz);
            quat2mat(qw * inv, qx * inv, qy * inv, qz * inv, sR);
            const float* qt = tgt + b * 4 * NC + cls * 4;  // unit-norm
            quat2mat(qt[0], qt[1], qt[2], qt[3], sR + 9);
        }
    }
    __syncthreads();

    const int issym = s_issym;
    const int cls = s_cls;
    const float* __restrict__ mp = pts + (size_t)cls * NP * 3;
    const int p0 = pc * PPB + tid;    // this thread's two p's
    const int p1 = p0 + TPB;

    if (!issym) {
        if (qc == 0) {
            // Pointwise |(Rp-Rt) x|^2 for p0, p1.
            float D0 = sR[0] - sR[9],  D1 = sR[1] - sR[10],
                  D2 = sR[2] - sR[11];
            float D3 = sR[3] - sR[12], D4 = sR[4] - sR[13],
                  D5 = sR[5] - sR[14];
            float D6 = sR[6] - sR[15], D7 = sR[7] - sR[16],
                  D8 = sR[8] - sR[17];
#pragma unroll
            for (int pi = 0; pi < 2; pi++) {
                int p = pi ? p1 : p0;
                float x = mp[3 * p + 0], y = mp[3 * p + 1], z = mp[3 * p + 2];
                float dx = D0 * x + D1 * y + D2 * z;
                float dy = D3 * x + D4 * y + D5 * z;
                float dz = D6 * x + D7 * y + D8 * z;
                g_dmin[b][0][p] = dx * dx + dy * dy + dz * dz;
            }
        }
    } else {
        // ---- heavy: fill this block's 256-q target tile ----
        {
            float T0 = sR[9],  T1 = sR[10], T2 = sR[11];
            float T3 = sR[12], T4 = sR[13], T5 = sR[14];
            float T6 = sR[15], T7 = sR[16], T8 = sR[17];
#pragma unroll
            for (int qq = tid; qq < QPB; qq += TPB) {
                int q = qc * QPB + qq;
                float x = mp[3 * q + 0], y = mp[3 * q + 1], z = mp[3 * q + 2];
                float tx = T0 * x + T1 * y + T2 * z;
                float ty = T3 * x + T4 * y + T5 * z;
                float tz = T6 * x + T7 * y + T8 * z;
                s_pt[qq] =
                    make_float4(tx, ty, tz, tx * tx + ty * ty + tz * tz);
            }
        }
        // predicted-rotated p0, p1
        float px0, py0, pz0, px1, py1, pz1;
        {
            float P0 = sR[0], P1 = sR[1], P2 = sR[2];
            float P3 = sR[3], P4 = sR[4], P5 = sR[5];
            float P6 = sR[6], P7 = sR[7], P8 = sR[8];
            float x = mp[3 * p0 + 0], y = mp[3 * p0 + 1], z = mp[3 * p0 + 2];
            px0 = P0 * x + P1 * y + P2 * z;
            py0 = P3 * x + P4 * y + P5 * z;
            pz0 = P6 * x + P7 * y + P8 * z;
            x = mp[3 * p1 + 0]; y = mp[3 * p1 + 1]; z = mp[3 * p1 + 2];
            px1 = P0 * x + P1 * y + P2 * z;
            py1 = P3 * x + P4 * y + P5 * z;
            pz1 = P6 * x + P7 * y + P8 * z;
        }
        __syncthreads();

        const float a0x = -2.f * px0, a0y = -2.f * py0, a0z = -2.f * pz0;
        const float a1x = -2.f * px1, a1y = -2.f * py1, a1z = -2.f * pz1;
        const float INF = 3.402823466e38f;
        float m0a = INF, m0b = INF, m1a = INF, m1b = INF;

#pragma unroll 4
        for (int j = 0; j < QPB / 2; j++) {
            float4 t0 = s_pt[2 * j];
            float4 t1 = s_pt[2 * j + 1];
            float v;
            v = fmaf(a0x, t0.x, t0.w);
            v = fmaf(a0y, t0.y, v);
            v = fmaf(a0z, t0.z, v);
            m0a = fminf(m0a, v);
            v = fmaf(a1x, t0.x, t0.w);
            v = fmaf(a1y, t0.y, v);
            v = fmaf(a1z, t0.z, v);
            m1a = fminf(m1a, v);
            v = fmaf(a0x, t1.x, t1.w);
            v = fmaf(a0y, t1.y, v);
            v = fmaf(a0z, t1.z, v);
            m0b = fminf(m0b, v);
            v = fmaf(a1x, t1.x, t1.w);
            v = fmaf(a1y, t1.y, v);
            v = fmaf(a1z, t1.z, v);
            m1b = fminf(m1b, v);
        }
        g_dmin[b][qc][p0] =
            fminf(m0a, m0b) + (px0 * px0 + py0 * py0 + pz0 * pz0);
        g_dmin[b][qc][p1] =
            fminf(m1a, m1b) + (px1 * px1 + py1 * py1 + pz1 * pz1);
    }

    // ---- release + per-b ticket (tid0-only fence; bar orders all stores) ----
    __syncthreads();
    if (tid == 0) {
        __threadfence();      // release this block's g_dmin stores
        int t = atomicAdd(&g_ticket_b[b], 1);
        s_lastb = (t == PC * QC - 1) ? 1 : 0;
        if (t == PC * QC - 1) __threadfence();   // acquire peers' stores
    }
    __syncthreads();
    if (!s_lastb) return;

    // ---- combine for ROI b (16th block; data is L2-hot) ----
    float acc = 0.f;
#pragma unroll
    for (int i = 0; i < NP / TPB; i++) {
        int p = tid + i * TPB;
        float dv = __ldcg(&g_dmin[b][0][p]);
        if (issym) {
#pragma unroll
            for (int k = 1; k < QC; k++)
                dv = fminf(dv, __ldcg(&g_dmin[b][k][p]));
        }
        acc += dv;
    }
    float tot = block_reduce_128(acc, s_red, tid);
    if (tid == 0) {
        g_partials[b] = tot;
        __threadfence();      // release partial
        unsigned t = atomicAdd(&g_ticket, 1u);
        s_lastg = (t == NB - 1) ? 1 : 0;
        if (t == NB - 1) __threadfence();        // acquire all partials
    }
    __syncthreads();
    if (!s_lastg) return;

    // ---- final: fixed-order 128-way sum, write scalar, reset tickets ----
    float v = __ldcg(&g_partials[tid]);
    float total = block_reduce_128(v, s_red, tid);
    g_ticket_b[tid] = 0;       // reset per-b tickets for next replay
    if (tid == 0) {
        out[0] = total * (1.0f / (2.0f * NB * NP));
        g_ticket = 0;
    }
}

extern "C" void kernel_launch(void* const* d_in, const int* in_sizes, int n_in,
                              void* d_out, int out_size) {
    const float* pred = (const float*)d_in[0];
    const float* tgt  = (const float*)d_in[1];
    const float* wt   = (const float*)d_in[2];
    const float* pts  = (const float*)d_in[3];
    const float* sym  = (const float*)d_in[4];
    float* out = (float*)d_out;

    pm_fused_kernel<<<GRID1, TPB>>>(pred, tgt, wt, pts, sym, out);
}